// round 2
// baseline (speedup 1.0000x reference)
#include <cuda_runtime.h>
#include <cuda_bf16.h>
#include <cstdint>

#define D            128
#define S            16
#define WARPS_PB     14
#define ITEM_TILE    4
#define ITEMS_PB     (WARPS_PB * ITEM_TILE)   // 56
#define BLOCK_THREADS (WARPS_PB * 32)         // 448

// smem: W (16384 floats) + per-warp duplicated-x buffers (ITEM_TILE*D*2 floats each)
#define XDUP_FLOATS  (ITEM_TILE * D * 2)      // 1024
#define SMEM_FLOATS  (D * D + WARPS_PB * XDUP_FLOATS)
#define SMEM_BYTES   (SMEM_FLOATS * 4)        // 122880 B

__device__ __forceinline__ unsigned long long pack2(float a, float b) {
    unsigned long long r;
    asm("mov.b64 %0, {%1, %2};" : "=l"(r) : "f"(a), "f"(b));
    return r;
}
__device__ __forceinline__ void unpack2(unsigned long long v, float& a, float& b) {
    asm("mov.b64 {%0, %1}, %2;" : "=f"(a), "=f"(b) : "l"(v));
}
__device__ __forceinline__ unsigned long long fma2(unsigned long long a,
                                                   unsigned long long b,
                                                   unsigned long long c) {
    unsigned long long d;
    asm("fma.rn.f32x2 %0, %1, %2, %3;" : "=l"(d) : "l"(a), "l"(b), "l"(c));
    return d;
}

__global__ __launch_bounds__(BLOCK_THREADS, 1)
void kgcn_kernel(const int* __restrict__ u,
                 const int* __restrict__ v,
                 const int* __restrict__ adj_ent,
                 const int* __restrict__ adj_rel,
                 const float* __restrict__ usr,
                 const float* __restrict__ ent,
                 const float* __restrict__ rel,
                 const float* __restrict__ W,
                 const float* __restrict__ bias,
                 float* __restrict__ out,
                 int B)
{
    extern __shared__ float smem[];
    float* Wsh = smem;                                   // 16384 floats

    const int tid  = threadIdx.x;
    const int lane = tid & 31;
    const int wid  = tid >> 5;

    // ---- stage W into shared (row-major W[i*128 + j]) ----
    {
        const float4* Wg4 = (const float4*)W;
        float4* Ws4 = (float4*)Wsh;
        for (int i = tid; i < (D * D) / 4; i += BLOCK_THREADS)
            Ws4[i] = Wg4[i];
    }
    __syncthreads();

    float* xd = smem + D * D + wid * XDUP_FLOATS;        // per-warp duplicated x

    const int base = (blockIdx.x * WARPS_PB + wid) * ITEM_TILE;

    const float4* usr4 = (const float4*)usr;
    const float4* ent4 = (const float4*)ent;
    const float4* rel4 = (const float4*)rel;

    // Lane owns dims j = lane*4 + m (float4 per lane) -- consistent everywhere.
    float4 ue[ITEM_TILE];    // user embedding
    float4 mg[ITEM_TILE];    // attention-weighted neighbor message

    #pragma unroll
    for (int t = 0; t < ITEM_TILE; t++) {
        int item = base + t;
        int cit  = item < B ? item : (B - 1);    // clamp (deterministic, no OOB write)
        const int iu = u[cit];
        const int iv = v[cit];

        const float4 uex = usr4[(size_t)iu * 32 + lane];
        ue[t] = uex;
        const float4 rp = ent4[(size_t)iv * 32 + lane];

        // load neighbor-entity indices early + prefetch their rows to L2,
        // so the msg-phase gathers hit L2 instead of DRAM.
        int eix[S];
        #pragma unroll
        for (int s = 0; s < S; s++)
            eix[s] = __ldg(&adj_ent[iv * S + s]);
        #pragma unroll
        for (int s = 0; s < S; s++) {
            const float4* p = ent4 + (size_t)eix[s] * 32 + lane;
            asm volatile("prefetch.global.L2 [%0];" :: "l"(p));
        }

        // -- attention scores: sc[s] = dot(u_emb, rel_table[adj_rel[v,s]]) --
        float sc[S];
        #pragma unroll
        for (int s = 0; s < S; s++) {
            int ridx = __ldg(&adj_rel[iv * S + s]);
            float4 r4 = rel4[(size_t)ridx * 32 + lane];
            float p = uex.x * r4.x + uex.y * r4.y + uex.z * r4.z + uex.w * r4.w;
            #pragma unroll
            for (int o = 16; o > 0; o >>= 1)
                p += __shfl_xor_sync(0xffffffffu, p, o);
            sc[s] = p;   // replicated in all lanes
        }

        // -- softmax over S --
        float mx = sc[0];
        #pragma unroll
        for (int s = 1; s < S; s++) mx = fmaxf(mx, sc[s]);
        float sum = 0.f;
        #pragma unroll
        for (int s = 0; s < S; s++) { sc[s] = __expf(sc[s] - mx); sum += sc[s]; }
        const float inv = __frcp_rn(sum);

        // -- message: msg = sum_s attn[s] * ent_table[adj_ent[v,s]] --
        float4 msg = make_float4(0.f, 0.f, 0.f, 0.f);
        #pragma unroll
        for (int s = 0; s < S; s++) {
            float4 e4 = ent4[(size_t)eix[s] * 32 + lane];
            float a = sc[s] * inv;
            msg.x = fmaf(a, e4.x, msg.x);
            msg.y = fmaf(a, e4.y, msg.y);
            msg.z = fmaf(a, e4.z, msg.z);
            msg.w = fmaf(a, e4.w, msg.w);
        }
        mg[t] = msg;

        // x0 = msg + rep0 -> shared, DUPLICATED ({x,x} pairs) for packed broadcast
        float4 x0 = make_float4(msg.x + rp.x, msg.y + rp.y, msg.z + rp.z, msg.w + rp.w);
        float4* dst = (float4*)(xd + t * (2 * D) + lane * 8);
        dst[0] = make_float4(x0.x, x0.x, x0.y, x0.y);
        dst[1] = make_float4(x0.z, x0.z, x0.w, x0.w);
    }
    __syncwarp();

    const float4 b4 = ((const float4*)bias)[lane];
    const unsigned long long bp0 = pack2(b4.x, b4.y);
    const unsigned long long bp1 = pack2(b4.z, b4.w);
    unsigned long long acc[ITEM_TILE][2];

    // ---- 2 iterations: rep = relu((msg + rep) @ W + b), packed f32x2 FMA ----
    #pragma unroll
    for (int iter = 0; iter < 2; iter++) {
        #pragma unroll
        for (int t = 0; t < ITEM_TILE; t++) { acc[t][0] = bp0; acc[t][1] = bp1; }

        #pragma unroll 4
        for (int i2 = 0; i2 < D / 2; i2++) {
            const float* wrow = Wsh + (2 * i2) * D + lane * 4;
            const ulonglong2 wA = *(const ulonglong2*)(wrow);       // W[2i2  ][j pair0, pair1]
            const ulonglong2 wB = *(const ulonglong2*)(wrow + D);   // W[2i2+1][j pair0, pair1]
            #pragma unroll
            for (int t = 0; t < ITEM_TILE; t++) {
                // {x_{2i2} dup, x_{2i2+1} dup}
                const ulonglong2 xp = *(const ulonglong2*)(xd + t * (2 * D) + i2 * 4);
                acc[t][0] = fma2(xp.x, wA.x, acc[t][0]);
                acc[t][1] = fma2(xp.x, wA.y, acc[t][1]);
                acc[t][0] = fma2(xp.y, wB.x, acc[t][0]);
                acc[t][1] = fma2(xp.y, wB.y, acc[t][1]);
            }
        }

        if (iter == 0) {
            __syncwarp();   // all lanes done reading xd before overwrite
            #pragma unroll
            for (int t = 0; t < ITEM_TILE; t++) {
                float a0, a1, a2, a3;
                unpack2(acc[t][0], a0, a1);
                unpack2(acc[t][1], a2, a3);
                float x0 = mg[t].x + fmaxf(a0, 0.f);
                float x1 = mg[t].y + fmaxf(a1, 0.f);
                float x2 = mg[t].z + fmaxf(a2, 0.f);
                float x3 = mg[t].w + fmaxf(a3, 0.f);
                float4* dst = (float4*)(xd + t * (2 * D) + lane * 8);
                dst[0] = make_float4(x0, x0, x1, x1);
                dst[1] = make_float4(x2, x2, x3, x3);
            }
            __syncwarp();
        }
    }

    // ---- final: sigmoid(dot(u_emb, relu(rep))) ----
    #pragma unroll
    for (int t = 0; t < ITEM_TILE; t++) {
        float a0, a1, a2, a3;
        unpack2(acc[t][0], a0, a1);
        unpack2(acc[t][1], a2, a3);
        float p = ue[t].x * fmaxf(a0, 0.f)
                + ue[t].y * fmaxf(a1, 0.f)
                + ue[t].z * fmaxf(a2, 0.f)
                + ue[t].w * fmaxf(a3, 0.f);
        #pragma unroll
        for (int o = 16; o > 0; o >>= 1)
            p += __shfl_xor_sync(0xffffffffu, p, o);
        int item = base + t;
        if (lane == 0 && item < B)
            out[item] = 1.f / (1.f + __expf(-p));
    }
}

extern "C" void kernel_launch(void* const* d_in, const int* in_sizes, int n_in,
                              void* d_out, int out_size)
{
    const int*   u       = (const int*)d_in[0];
    const int*   v       = (const int*)d_in[1];
    const int*   adj_ent = (const int*)d_in[2];
    const int*   adj_rel = (const int*)d_in[3];
    const float* usr     = (const float*)d_in[4];
    const float* ent     = (const float*)d_in[5];
    const float* rel     = (const float*)d_in[6];
    const float* W       = (const float*)d_in[7];
    const float* bias    = (const float*)d_in[8];
    float* out = (float*)d_out;

    const int B = in_sizes[0];

    static bool attr_set = false;
    if (!attr_set) {
        cudaFuncSetAttribute(kgcn_kernel,
                             cudaFuncAttributeMaxDynamicSharedMemorySize,
                             SMEM_BYTES);
        attr_set = true;
    }

    dim3 grid((B + ITEMS_PB - 1) / ITEMS_PB);   // 147 blocks ~ 148 SMs, 1 block/SM
    kgcn_kernel<<<grid, BLOCK_THREADS, SMEM_BYTES>>>(
        u, v, adj_ent, adj_rel, usr, ent, rel, W, bias, out, B);
}